// round 9
// baseline (speedup 1.0000x reference)
#include <cuda_runtime.h>
#include <math_constants.h>

// Problem constants
#define Bsz 8
#define Nn  1032
#define Cc  768
#define Hh  12
#define HD  64
#define PFX 8

// Scratch (static device allocations; cudaMalloc is forbidden)
__device__ float g_K[(size_t)Bsz * Hh * Nn * HD];   // K [b,h,n,d], tf32-rounded
__device__ float g_V[(size_t)Bsz * Hh * Nn * HD];   // V [b,h,n,d], tf32-rounded
__device__ float g_AO[(size_t)Bsz * Nn * Cc];       // attention output [b,n,c]

// ---------------------------------------------------------------------------
// helpers
// ---------------------------------------------------------------------------
__device__ __forceinline__ float cvt_tf32(float x) {
    unsigned r;
    asm("cvt.rna.tf32.f32 %0, %1;" : "=r"(r) : "f"(x));
    return __uint_as_float(r);
}
__device__ __forceinline__ float4 cvt_tf32_4(float4 v) {
    return make_float4(cvt_tf32(v.x), cvt_tf32(v.y), cvt_tf32(v.z), cvt_tf32(v.w));
}
__device__ __forceinline__ void ldm4(unsigned r[4], unsigned addr) {
    asm volatile("ldmatrix.sync.aligned.m8n8.x4.shared.b16 {%0,%1,%2,%3}, [%4];"
                 : "=r"(r[0]), "=r"(r[1]), "=r"(r[2]), "=r"(r[3]) : "r"(addr));
}
__device__ __forceinline__ void mma8(float c[4], const unsigned a[4],
                                     unsigned b0, unsigned b1) {
    asm volatile(
        "mma.sync.aligned.m16n8k8.row.col.f32.tf32.tf32.f32 "
        "{%0,%1,%2,%3},{%4,%5,%6,%7},{%8,%9},{%0,%1,%2,%3};"
        : "+f"(c[0]), "+f"(c[1]), "+f"(c[2]), "+f"(c[3])
        : "r"(a[0]), "r"(a[1]), "r"(a[2]), "r"(a[3]), "r"(b0), "r"(b1));
}
__device__ __forceinline__ unsigned smem_u32(const void* p) {
    return (unsigned)__cvta_generic_to_shared(p);
}

// ---------------------------------------------------------------------------
// tf32 NT GEMM (R2 structure, proven): C[m,n] = sum_k A[m,k]*Bm[n,k] + bias[n]
// 128x128 tile, k-tile 32, 256 threads (8 warps), warp tile 64x32.
// MODE 1: scatter tf32-rounded output into g_K / g_V.  MODE 2: row-major Cout.
// ---------------------------------------------------------------------------
#define SAS 36   // smem row stride floats (144B = 9*16B -> conflict-free ldmatrix)

template <int MODE>
__global__ void __launch_bounds__(256) gemm_tf32(
        const float* __restrict__ A, const float* __restrict__ Bm,
        const float* __restrict__ bias, float* __restrict__ Cout,
        int M, int Nout, int K) {
    __shared__ float sA[128 * SAS];
    __shared__ float sB[128 * SAS];

    const float* Ap = (MODE == 2) ? (const float*)g_AO : A;

    int tid = threadIdx.x;
    int lane = tid & 31;
    int w = tid >> 5;
    int wm = w >> 2, wn = w & 3;          // warp grid 2 x 4
    int m0 = blockIdx.y * 128, n0 = blockIdx.x * 128;

    int frow = tid >> 1;
    int fcol = (tid & 1) * 16;
    const float* Aptr = Ap + (size_t)(m0 + frow) * K + fcol;
    const float* Bptr = Bm + (size_t)(n0 + frow) * K + fcol;
    bool aval = (m0 + frow) < M;

    float4 ra[4], rb[4];
#pragma unroll
    for (int i = 0; i < 4; i++) {
        ra[i] = aval ? *(const float4*)(Aptr + i * 4) : make_float4(0.f, 0.f, 0.f, 0.f);
        rb[i] = *(const float4*)(Bptr + i * 4);
    }

    float acc[4][4][4] = {};

    unsigned sAu = smem_u32(sA), sBu = smem_u32(sB);
    int l7 = lane & 7, q = lane >> 3;
    unsigned aBase = sAu + (((wm * 64 + l7 + (q & 1) * 8) * SAS + (q >> 1) * 4) << 2);
    unsigned bBase = sBu + (((wn * 32 + l7 + (q >> 1) * 8) * SAS + (q & 1) * 4) << 2);

    int nkt = K / 32;
    for (int kt = 0; kt < nkt; kt++) {
        __syncthreads();
#pragma unroll
        for (int i = 0; i < 4; i++) {
            *(float4*)&sA[frow * SAS + fcol + i * 4] = cvt_tf32_4(ra[i]);
            *(float4*)&sB[frow * SAS + fcol + i * 4] = cvt_tf32_4(rb[i]);
        }
        __syncthreads();
        if (kt + 1 < nkt) {
#pragma unroll
            for (int i = 0; i < 4; i++) {
                ra[i] = aval ? *(const float4*)(Aptr + (kt + 1) * 32 + i * 4)
                             : make_float4(0.f, 0.f, 0.f, 0.f);
                rb[i] = *(const float4*)(Bptr + (kt + 1) * 32 + i * 4);
            }
        }
#pragma unroll
        for (int k8 = 0; k8 < 4; k8++) {
            unsigned af[4][4], bf[2][4];
#pragma unroll
            for (int mi = 0; mi < 4; mi++)
                ldm4(af[mi], aBase + mi * (16 * SAS * 4) + k8 * 32);
#pragma unroll
            for (int nj = 0; nj < 2; nj++)
                ldm4(bf[nj], bBase + nj * (16 * SAS * 4) + k8 * 32);
#pragma unroll
            for (int mi = 0; mi < 4; mi++)
#pragma unroll
                for (int ni = 0; ni < 4; ni++)
                    mma8(acc[mi][ni], af[mi],
                         bf[ni >> 1][(ni & 1) * 2], bf[ni >> 1][(ni & 1) * 2 + 1]);
        }
    }

    int r0base = m0 + wm * 64 + (lane >> 2);
    int cbase = n0 + wn * 32 + 2 * (lane & 3);
#pragma unroll
    for (int mi = 0; mi < 4; mi++) {
#pragma unroll
        for (int ni = 0; ni < 4; ni++) {
            int c = cbase + ni * 8;
            float bv0 = bias[c], bv1 = bias[c + 1];
#pragma unroll
            for (int half = 0; half < 2; half++) {
                int m = r0base + mi * 16 + half * 8;
                if (m >= M) continue;
                float v0 = acc[mi][ni][half * 2 + 0] + bv0;
                float v1 = acc[mi][ni][half * 2 + 1] + bv1;
                if (MODE == 2) {
                    Cout[(size_t)m * Nout + c]     = v0;
                    Cout[(size_t)m * Nout + c + 1] = v1;
                } else {
                    int bb = m / Nn;
                    int nn = m - bb * Nn;
#pragma unroll
                    for (int e = 0; e < 2; e++) {
                        int n = c + e;
                        float v = cvt_tf32(e ? v1 : v0);   // pre-round for attention
                        if (n < Cc) {
                            int h = n >> 6, d = n & 63;
                            g_K[(((size_t)bb * Hh + h) * Nn + nn) * HD + d] = v;
                        } else {
                            int o = n - Cc;
                            int h = o >> 6, d = o & 63;
                            g_V[(((size_t)bb * Hh + h) * Nn + nn) * HD + d] = v;
                        }
                    }
                }
            }
        }
    }
}

// ---------------------------------------------------------------------------
// Fused flash attention (R8 structure, 624us proven). R9 change: the 63-entry
// gaussian LUT lives in static smem, computed in-kernel -> the 64 LDG per
// thread per j-tile become LDS (and the init kernel + g_lut global go away).
// 128 threads (4 warps), i-tile 64, warp owns 16 rows, P aliased onto Kj.
// ---------------------------------------------------------------------------
#define SKS 68   // 272B = 17 * 16B -> conflict-free ldmatrix
#define ATTN_SMEM (3 * 64 * SKS * 4)

__global__ void __launch_bounds__(128, 4) attn_tf32() {
    extern __shared__ float smem[];
    float* sKi  = smem;
    float* sKjP = sKi + 64 * SKS;     // Kj during S phase, P afterwards
    float* sV   = sKjP + 64 * SKS;    // row-major [j][d], tf32
    __shared__ float slut[64];        // gaussian 1-D window LUT

    int tid = threadIdx.x;
    int lane = tid & 31;
    int w = tid >> 5;
    int it = blockIdx.x, h = blockIdx.y, b = blockIdx.z;
    int i0 = it * 64;

    // LUT: exp(-((t-31)/(5*sqrt(2)))^2), t in [0,63)
    if (tid < 63) {
        const float c = 0.14142135623730951f;
        float xx = (float)(tid - 31) * c;
        slut[tid] = expf(-xx * xx);
    }

    const float* Kbh = g_K + ((size_t)(b * Hh + h)) * Nn * HD;
    const float* Vbh = g_V + ((size_t)(b * Hh + h)) * Nn * HD;

    for (int idx = tid; idx < 64 * 16; idx += 128) {
        int r = idx >> 4, c4 = (idx & 15) << 2;
        int gi = i0 + r;
        float4 v = (gi < Nn) ? *(const float4*)(Kbh + (size_t)gi * HD + c4)
                             : make_float4(0.f, 0.f, 0.f, 0.f);
        *(float4*)&sKi[r * SKS + c4] = v;
    }

    float o[8][4] = {};
    float mrun0 = -CUDART_INF_F, mrun1 = -CUDART_INF_F;
    float lrun0 = 0.f, lrun1 = 0.f;

    unsigned sKiu = smem_u32(sKi), sKjPu = smem_u32(sKjP);
    int l7 = lane & 7, q = lane >> 3;
    unsigned aOff = (((w * 16 + l7 + (q & 1) * 8) * SKS + (q >> 1) * 4) << 2);
    unsigned bOff = (((l7 + (q >> 1) * 8) * SKS + (q & 1) * 4) << 2);
    unsigned aKi = sKiu + aOff;
    unsigned aP  = sKjPu + aOff;
    unsigned bKj = sKjPu + bOff;
    int vb = (lane & 3) * SKS + (lane >> 2);   // scalar V fragment base

    int rloc0 = w * 16 + (lane >> 2);
    int rloc1 = rloc0 + 8;
    int pc = 2 * (lane & 3);

    for (int jt = 0; jt < 17; jt++) {
        int j0 = jt * 64;
        __syncthreads();    // prior O-phase reads done (also covers slut/Ki fill)
        for (int idx = tid; idx < 64 * 16; idx += 128) {
            int r = idx >> 4, c4 = (idx & 15) << 2;
            int gj = j0 + r;
            float4 kv, vv;
            if (gj < Nn) {
                kv = *(const float4*)(Kbh + (size_t)gj * HD + c4);
                vv = *(const float4*)(Vbh + (size_t)gj * HD + c4);
            } else {
                kv = make_float4(0.f, 0.f, 0.f, 0.f);
                vv = kv;
            }
            *(float4*)&sKjP[r * SKS + c4] = kv;
            *(float4*)&sV[r * SKS + c4]   = vv;
        }
        __syncthreads();

        // S = Ki . Kj^T
        float s[8][4] = {};
#pragma unroll
        for (int k8 = 0; k8 < 8; k8++) {
            unsigned af[4];
            ldm4(af, aKi + k8 * 32);
#pragma unroll
            for (int n16 = 0; n16 < 4; n16++) {
                unsigned bf[4];
                ldm4(bf, bKj + n16 * (16 * SKS * 4) + k8 * 32);
                mma8(s[2 * n16 + 0], af, bf[0], bf[1]);
                mma8(s[2 * n16 + 1], af, bf[2], bf[3]);
            }
        }

        // scale + gaussian bias (smem LUT) + mask
        int gi0 = i0 + rloc0, gi1 = i0 + rloc1;
#pragma unroll
        for (int f = 0; f < 8; f++) {
#pragma unroll
            for (int e = 0; e < 4; e++) {
                int gi = (e < 2) ? gi0 : gi1;
                int gj = j0 + f * 8 + pc + (e & 1);
                float val = s[f][e] * 0.125f;
                if (gi >= PFX && gj >= PFX && gi < Nn && gj < Nn) {
                    int ia = gi - PFX, ja = gj - PFX;
                    val += slut[(ia >> 5) - (ja >> 5) + 31] *
                           slut[(ia & 31) - (ja & 31) + 31];
                }
                if (gj >= Nn) val = -CUDART_INF_F;
                s[f][e] = val;
            }
        }

        // online softmax
        float mt0 = -CUDART_INF_F, mt1 = -CUDART_INF_F;
#pragma unroll
        for (int f = 0; f < 8; f++) {
            mt0 = fmaxf(mt0, fmaxf(s[f][0], s[f][1]));
            mt1 = fmaxf(mt1, fmaxf(s[f][2], s[f][3]));
        }
#pragma unroll
        for (int off = 1; off <= 2; off <<= 1) {
            mt0 = fmaxf(mt0, __shfl_xor_sync(0xffffffffu, mt0, off));
            mt1 = fmaxf(mt1, __shfl_xor_sync(0xffffffffu, mt1, off));
        }
        float mn0 = fmaxf(mrun0, mt0), mn1 = fmaxf(mrun1, mt1);
        float fac0 = __expf(mrun0 - mn0), fac1 = __expf(mrun1 - mn1);
        mrun0 = mn0; mrun1 = mn1;
        float st0 = 0.f, st1 = 0.f;
#pragma unroll
        for (int f = 0; f < 8; f++) {
            s[f][0] = __expf(s[f][0] - mn0);
            s[f][1] = __expf(s[f][1] - mn0);
            s[f][2] = __expf(s[f][2] - mn1);
            s[f][3] = __expf(s[f][3] - mn1);
            st0 += s[f][0] + s[f][1];
            st1 += s[f][2] + s[f][3];
        }
#pragma unroll
        for (int off = 1; off <= 2; off <<= 1) {
            st0 += __shfl_xor_sync(0xffffffffu, st0, off);
            st1 += __shfl_xor_sync(0xffffffffu, st1, off);
        }
        lrun0 = lrun0 * fac0 + st0;
        lrun1 = lrun1 * fac1 + st1;
#pragma unroll
        for (int f = 0; f < 8; f++) {
            o[f][0] *= fac0; o[f][1] *= fac0;
            o[f][2] *= fac1; o[f][3] *= fac1;
        }

        __syncthreads();    // all warps' S-phase reads of sKjP done

        // stage P (tf32) into the Kj buffer
#pragma unroll
        for (int f = 0; f < 8; f++) {
            *(float2*)&sKjP[rloc0 * SKS + f * 8 + pc] =
                make_float2(cvt_tf32(s[f][0]), cvt_tf32(s[f][1]));
            *(float2*)&sKjP[rloc1 * SKS + f * 8 + pc] =
                make_float2(cvt_tf32(s[f][2]), cvt_tf32(s[f][3]));
        }
        __syncthreads();

        // O += P @ V  (B-frags via conflict-free scalar LDS from row-major sV)
#pragma unroll
        for (int k8 = 0; k8 < 8; k8++) {
            unsigned af[4];
            ldm4(af, aP + k8 * 32);
            int base = k8 * 8 * SKS + vb;
#pragma unroll
            for (int g = 0; g < 4; g++) {
#pragma unroll
                for (int sn = 0; sn < 2; sn++) {
                    int fi = base + g * 16 + sn * 8;
                    unsigned b0 = __float_as_uint(sV[fi]);
                    unsigned b1 = __float_as_uint(sV[fi + 4 * SKS]);
                    mma8(o[2 * g + sn], af, b0, b1);
                }
            }
        }
    }

    // normalize + write [b,n,c]
    int gi0 = i0 + rloc0, gi1 = i0 + rloc1;
    float inv0 = 1.f / lrun0, inv1 = 1.f / lrun1;
    int cb = h * HD + pc;
#pragma unroll
    for (int f = 0; f < 8; f++) {
        int col = cb + f * 8;
        if (gi0 < Nn) {
            g_AO[((size_t)b * Nn + gi0) * Cc + col]     = o[f][0] * inv0;
            g_AO[((size_t)b * Nn + gi0) * Cc + col + 1] = o[f][1] * inv0;
        }
        if (gi1 < Nn) {
            g_AO[((size_t)b * Nn + gi1) * Cc + col]     = o[f][2] * inv1;
            g_AO[((size_t)b * Nn + gi1) * Cc + col + 1] = o[f][3] * inv1;
        }
    }
}

extern "C" void kernel_launch(void* const* d_in, const int* in_sizes, int n_in,
                              void* d_out, int out_size) {
    (void)in_sizes; (void)n_in; (void)out_size;
    const float* x      = (const float*)d_in[0];
    const float* qkv_w  = (const float*)d_in[1];
    const float* qkv_b  = (const float*)d_in[2];
    const float* proj_w = (const float*)d_in[3];
    const float* proj_b = (const float*)d_in[4];
    float* out = (float*)d_out;

    static bool attr_done = false;
    if (!attr_done) {
        cudaFuncSetAttribute(attn_tf32,
                             cudaFuncAttributeMaxDynamicSharedMemorySize, ATTN_SMEM);
        attr_done = true;
    }

    // KV GEMM (Q slab of qkv_w is dead code in the reference)
    gemm_tf32<1><<<dim3((2 * Cc) / 128, (Bsz * Nn + 127) / 128), 256>>>(
        x, qkv_w + (size_t)Cc * Cc, qkv_b + Cc, nullptr,
        Bsz * Nn, 2 * Cc, Cc);

    attn_tf32<<<dim3(17, Hh, Bsz), 128, ATTN_SMEM>>>();

    // Projection GEMM
    gemm_tf32<2><<<dim3(Cc / 128, (Bsz * Nn + 127) / 128), 256>>>(
        nullptr, proj_w, proj_b, out,
        Bsz * Nn, Cc, Cc);
}

// round 12
// speedup vs baseline: 1.0647x; 1.0647x over previous
#include <cuda_runtime.h>
#include <math_constants.h>

// Problem constants
#define Bsz 8
#define Nn  1032
#define Cc  768
#define Hh  12
#define HD  64
#define PFX 8

// Scratch (static device allocations; cudaMalloc is forbidden)
__device__ float g_K[(size_t)Bsz * Hh * Nn * HD];   // K [b,h,n,d], tf32-rounded
__device__ float g_V[(size_t)Bsz * Hh * Nn * HD];   // V [b,h,n,d], tf32-rounded
__device__ float g_AO[(size_t)Bsz * Nn * Cc];       // attention output [b,n,c]
__device__ float g_lut[64];                          // gaussian 1-D window LUT

__global__ void init_lut_kernel() {
    int t = threadIdx.x;
    if (t < 63) {
        const float c = 0.14142135623730951f;   // 1/(5*sqrt(2))
        float x = (float)(t - 31) * c;
        g_lut[t] = expf(-x * x);
    }
}

// ---------------------------------------------------------------------------
// helpers
// ---------------------------------------------------------------------------
__device__ __forceinline__ float cvt_tf32(float x) {
    unsigned r;
    asm("cvt.rna.tf32.f32 %0, %1;" : "=r"(r) : "f"(x));
    return __uint_as_float(r);
}
__device__ __forceinline__ float4 cvt_tf32_4(float4 v) {
    return make_float4(cvt_tf32(v.x), cvt_tf32(v.y), cvt_tf32(v.z), cvt_tf32(v.w));
}
__device__ __forceinline__ void ldm4(unsigned r[4], unsigned addr) {
    asm volatile("ldmatrix.sync.aligned.m8n8.x4.shared.b16 {%0,%1,%2,%3}, [%4];"
                 : "=r"(r[0]), "=r"(r[1]), "=r"(r[2]), "=r"(r[3]) : "r"(addr));
}
__device__ __forceinline__ void mma8(float c[4], const unsigned a[4],
                                     unsigned b0, unsigned b1) {
    asm volatile(
        "mma.sync.aligned.m16n8k8.row.col.f32.tf32.tf32.f32 "
        "{%0,%1,%2,%3},{%4,%5,%6,%7},{%8,%9},{%0,%1,%2,%3};"
        : "+f"(c[0]), "+f"(c[1]), "+f"(c[2]), "+f"(c[3])
        : "r"(a[0]), "r"(a[1]), "r"(a[2]), "r"(a[3]), "r"(b0), "r"(b1));
}
__device__ __forceinline__ unsigned smem_u32(const void* p) {
    return (unsigned)__cvta_generic_to_shared(p);
}
__device__ __forceinline__ void cpa16p(unsigned dst, const float* src, int srcsz) {
    asm volatile("cp.async.cg.shared.global [%0], [%1], 16, %2;"
                 :: "r"(dst), "l"(src), "r"(srcsz));
}
__device__ __forceinline__ void cpa_commit() {
    asm volatile("cp.async.commit_group;" ::: "memory");
}
__device__ __forceinline__ void cpa_wait0() {
    asm volatile("cp.async.wait_group 0;" ::: "memory");
}

// ---------------------------------------------------------------------------
// tf32 NT GEMM (R2 structure, proven): C[m,n] = sum_k A[m,k]*Bm[n,k] + bias[n]
// 128x128 tile, k-tile 32, 256 threads (8 warps), warp tile 64x32.
// MODE 1: scatter tf32-rounded output into g_K / g_V.  MODE 2: row-major Cout.
// ---------------------------------------------------------------------------
#define SAS 36   // smem row stride floats (144B = 9*16B -> conflict-free ldmatrix)

template <int MODE>
__global__ void __launch_bounds__(256) gemm_tf32(
        const float* __restrict__ A, const float* __restrict__ Bm,
        const float* __restrict__ bias, float* __restrict__ Cout,
        int M, int Nout, int K) {
    __shared__ float sA[128 * SAS];
    __shared__ float sB[128 * SAS];

    const float* Ap = (MODE == 2) ? (const float*)g_AO : A;

    int tid = threadIdx.x;
    int lane = tid & 31;
    int w = tid >> 5;
    int wm = w >> 2, wn = w & 3;          // warp grid 2 x 4
    int m0 = blockIdx.y * 128, n0 = blockIdx.x * 128;

    int frow = tid >> 1;
    int fcol = (tid & 1) * 16;
    const float* Aptr = Ap + (size_t)(m0 + frow) * K + fcol;
    const float* Bptr = Bm + (size_t)(n0 + frow) * K + fcol;
    bool aval = (m0 + frow) < M;

    float4 ra[4], rb[4];
#pragma unroll
    for (int i = 0; i < 4; i++) {
        ra[i] = aval ? *(const float4*)(Aptr + i * 4) : make_float4(0.f, 0.f, 0.f, 0.f);
        rb[i] = *(const float4*)(Bptr + i * 4);
    }

    float acc[4][4][4] = {};

    unsigned sAu = smem_u32(sA), sBu = smem_u32(sB);
    int l7 = lane & 7, q = lane >> 3;
    unsigned aBase = sAu + (((wm * 64 + l7 + (q & 1) * 8) * SAS + (q >> 1) * 4) << 2);
    unsigned bBase = sBu + (((wn * 32 + l7 + (q >> 1) * 8) * SAS + (q & 1) * 4) << 2);

    int nkt = K / 32;
    for (int kt = 0; kt < nkt; kt++) {
        __syncthreads();
#pragma unroll
        for (int i = 0; i < 4; i++) {
            *(float4*)&sA[frow * SAS + fcol + i * 4] = cvt_tf32_4(ra[i]);
            *(float4*)&sB[frow * SAS + fcol + i * 4] = cvt_tf32_4(rb[i]);
        }
        __syncthreads();
        if (kt + 1 < nkt) {
#pragma unroll
            for (int i = 0; i < 4; i++) {
                ra[i] = aval ? *(const float4*)(Aptr + (kt + 1) * 32 + i * 4)
                             : make_float4(0.f, 0.f, 0.f, 0.f);
                rb[i] = *(const float4*)(Bptr + (kt + 1) * 32 + i * 4);
            }
        }
#pragma unroll
        for (int k8 = 0; k8 < 4; k8++) {
            unsigned af[4][4], bf[2][4];
#pragma unroll
            for (int mi = 0; mi < 4; mi++)
                ldm4(af[mi], aBase + mi * (16 * SAS * 4) + k8 * 32);
#pragma unroll
            for (int nj = 0; nj < 2; nj++)
                ldm4(bf[nj], bBase + nj * (16 * SAS * 4) + k8 * 32);
#pragma unroll
            for (int mi = 0; mi < 4; mi++)
#pragma unroll
                for (int ni = 0; ni < 4; ni++)
                    mma8(acc[mi][ni], af[mi],
                         bf[ni >> 1][(ni & 1) * 2], bf[ni >> 1][(ni & 1) * 2 + 1]);
        }
    }

    int r0base = m0 + wm * 64 + (lane >> 2);
    int cbase = n0 + wn * 32 + 2 * (lane & 3);
#pragma unroll
    for (int mi = 0; mi < 4; mi++) {
#pragma unroll
        for (int ni = 0; ni < 4; ni++) {
            int c = cbase + ni * 8;
            float bv0 = bias[c], bv1 = bias[c + 1];
#pragma unroll
            for (int half = 0; half < 2; half++) {
                int m = r0base + mi * 16 + half * 8;
                if (m >= M) continue;
                float v0 = acc[mi][ni][half * 2 + 0] + bv0;
                float v1 = acc[mi][ni][half * 2 + 1] + bv1;
                if (MODE == 2) {
                    Cout[(size_t)m * Nout + c]     = v0;
                    Cout[(size_t)m * Nout + c + 1] = v1;
                } else {
                    int bb = m / Nn;
                    int nn = m - bb * Nn;
#pragma unroll
                    for (int e = 0; e < 2; e++) {
                        int n = c + e;
                        float v = cvt_tf32(e ? v1 : v0);   // pre-round for attention
                        if (n < Cc) {
                            int h = n >> 6, d = n & 63;
                            g_K[(((size_t)bb * Hh + h) * Nn + nn) * HD + d] = v;
                        } else {
                            int o = n - Cc;
                            int h = o >> 6, d = o & 63;
                            g_V[(((size_t)bb * Hh + h) * Nn + nn) * HD + d] = v;
                        }
                    }
                }
            }
        }
    }
}

// ---------------------------------------------------------------------------
// Fused flash attention. R10 changes vs R8 (623.7us proven):
//  - Ki A-fragments hoisted into registers (loop-invariant) -> Ki smem buffer
//    deleted; Ki staged through the Kj buffer pre-loop. smem 52.2->34.8 KB.
//  - Kj/V fills via cp.async (data pre-rounded; OOB rows via src-size=0).
//  - gaussian LUT back to __ldg from gmem (R9 smem LUT was neutral/negative).
// 128 threads (4 warps), i-tile 64, warp owns 16 rows, P aliased onto Kj.
// ---------------------------------------------------------------------------
#define SKS 68   // 272B = 17 * 16B -> conflict-free ldmatrix
#define ATTN_SMEM (2 * 64 * SKS * 4)

__global__ void __launch_bounds__(128, 4) attn_tf32() {
    extern __shared__ float smem[];
    float* sKjP = smem;               // Ki (pre-loop) / Kj (S phase) / P (O phase)
    float* sV   = sKjP + 64 * SKS;    // row-major [j][d], tf32

    int tid = threadIdx.x;
    int lane = tid & 31;
    int w = tid >> 5;
    int it = blockIdx.x, h = blockIdx.y, b = blockIdx.z;
    int i0 = it * 64;

    const float* Kbh = g_K + ((size_t)(b * Hh + h)) * Nn * HD;
    const float* Vbh = g_V + ((size_t)(b * Hh + h)) * Nn * HD;

    unsigned sKjPu = smem_u32(sKjP);
    int l7 = lane & 7, q = lane >> 3;
    unsigned aOff = (((w * 16 + l7 + (q & 1) * 8) * SKS + (q >> 1) * 4) << 2);
    unsigned bOff = (((l7 + (q >> 1) * 8) * SKS + (q & 1) * 4) << 2);
    unsigned aP  = sKjPu + aOff;
    unsigned bKj = sKjPu + bOff;
    int vb = (lane & 3) * SKS + (lane >> 2);   // scalar V fragment base

    // stage Ki through the Kj buffer, hoist A-fragments into registers
    for (int idx = tid; idx < 64 * 16; idx += 128) {
        int r = idx >> 4, c4 = (idx & 15) << 2;
        int gi = i0 + r;
        float4 v = (gi < Nn) ? *(const float4*)(Kbh + (size_t)gi * HD + c4)
                             : make_float4(0.f, 0.f, 0.f, 0.f);
        *(float4*)&sKjP[r * SKS + c4] = v;
    }
    __syncthreads();
    unsigned kif[8][4];
#pragma unroll
    for (int k8 = 0; k8 < 8; k8++)
        ldm4(kif[k8], aP + k8 * 32);
    // loop-top barrier orders these reads before the first Kj fill overwrite

    float o[8][4] = {};
    float mrun0 = -CUDART_INF_F, mrun1 = -CUDART_INF_F;
    float lrun0 = 0.f, lrun1 = 0.f;

    int rloc0 = w * 16 + (lane >> 2);
    int rloc1 = rloc0 + 8;
    int pc = 2 * (lane & 3);

    for (int jt = 0; jt < 17; jt++) {
        int j0 = jt * 64;
        __syncthreads();    // prior O-phase reads (and pre-loop kif loads) done
        // fill Kj + V via cp.async (zero-fill rows beyond N via src-size=0)
        for (int idx = tid; idx < 64 * 16; idx += 128) {
            int r = idx >> 4, c4 = (idx & 15) << 2;
            int gj = j0 + r;
            int gjc = (gj < Nn) ? gj : (Nn - 1);
            int sz = (gj < Nn) ? 16 : 0;
            unsigned off = (unsigned)((r * SKS + c4) << 2);
            cpa16p(sKjPu + off, Kbh + (size_t)gjc * HD + c4, sz);
            cpa16p(sKjPu + (unsigned)(64 * SKS * 4) + off,
                   Vbh + (size_t)gjc * HD + c4, sz);
        }
        cpa_commit();
        cpa_wait0();
        __syncthreads();

        // S = Ki . Kj^T   (A-frags from registers)
        float s[8][4] = {};
#pragma unroll
        for (int k8 = 0; k8 < 8; k8++) {
#pragma unroll
            for (int n16 = 0; n16 < 4; n16++) {
                unsigned bf[4];
                ldm4(bf, bKj + n16 * (16 * SKS * 4) + k8 * 32);
                mma8(s[2 * n16 + 0], kif[k8], bf[0], bf[1]);
                mma8(s[2 * n16 + 1], kif[k8], bf[2], bf[3]);
            }
        }

        // scale + gaussian bias + mask
        int gi0 = i0 + rloc0, gi1 = i0 + rloc1;
#pragma unroll
        for (int f = 0; f < 8; f++) {
#pragma unroll
            for (int e = 0; e < 4; e++) {
                int gi = (e < 2) ? gi0 : gi1;
                int gj = j0 + f * 8 + pc + (e & 1);
                float val = s[f][e] * 0.125f;
                if (gi >= PFX && gj >= PFX && gi < Nn && gj < Nn) {
                    int ia = gi - PFX, ja = gj - PFX;
                    val += __ldg(&g_lut[(ia >> 5) - (ja >> 5) + 31]) *
                           __ldg(&g_lut[(ia & 31) - (ja & 31) + 31]);
                }
                if (gj >= Nn) val = -CUDART_INF_F;
                s[f][e] = val;
            }
        }

        // online softmax
        float mt0 = -CUDART_INF_F, mt1 = -CUDART_INF_F;
#pragma unroll
        for (int f = 0; f < 8; f++) {
            mt0 = fmaxf(mt0, fmaxf(s[f][0], s[f][1]));
            mt1 = fmaxf(mt1, fmaxf(s[f][2], s[f][3]));
        }
#pragma unroll
        for (int off = 1; off <= 2; off <<= 1) {
            mt0 = fmaxf(mt0, __shfl_xor_sync(0xffffffffu, mt0, off));
            mt1 = fmaxf(mt1, __shfl_xor_sync(0xffffffffu, mt1, off));
        }
        float mn0 = fmaxf(mrun0, mt0), mn1 = fmaxf(mrun1, mt1);
        float fac0 = __expf(mrun0 - mn0), fac1 = __expf(mrun1 - mn1);
        mrun0 = mn0; mrun1 = mn1;
        float st0 = 0.f, st1 = 0.f;
#pragma unroll
        for (int f = 0; f < 8; f++) {
            s[f][0] = __expf(s[f][0] - mn0);
            s[f][1] = __expf(s[f][1] - mn0);
            s[f][2] = __expf(s[f][2] - mn1);
            s[f][3] = __expf(s[f][3] - mn1);
            st0 += s[f][0] + s[f][1];
            st1 += s[f][2] + s[f][3];
        }
#pragma unroll
        for (int off = 1; off <= 2; off <<= 1) {
            st0 += __shfl_xor_sync(0xffffffffu, st0, off);
            st1 += __shfl_xor_sync(0xffffffffu, st1, off);
        }
        lrun0 = lrun0 * fac0 + st0;
        lrun1 = lrun1 * fac1 + st1;
#pragma unroll
        for (int f = 0; f < 8; f++) {
            o[f][0] *= fac0; o[f][1] *= fac0;
            o[f][2] *= fac1; o[f][3] *= fac1;
        }

        __syncthreads();    // all warps' S-phase reads of sKjP done

        // stage P (tf32) into the Kj buffer
#pragma unroll
        for (int f = 0; f < 8; f++) {
            *(float2*)&sKjP[rloc0 * SKS + f * 8 + pc] =
                make_float2(cvt_tf32(s[f][0]), cvt_tf32(s[f][1]));
            *(float2*)&sKjP[rloc1 * SKS + f * 8 + pc] =
                make_float2(cvt_tf32(s[f][2]), cvt_tf32(s[f][3]));
        }
        __syncthreads();

        // O += P @ V  (B-frags via conflict-free scalar LDS from row-major sV)
#pragma unroll
        for (int k8 = 0; k8 < 8; k8++) {
            unsigned af[4];
            ldm4(af, aP + k8 * 32);
            int base = k8 * 8 * SKS + vb;
#pragma unroll
            for (int g = 0; g < 4; g++) {
#pragma unroll
                for (int sn = 0; sn < 2; sn++) {
                    int fi = base + g * 16 + sn * 8;
                    unsigned b0 = __float_as_uint(sV[fi]);
                    unsigned b1 = __float_as_uint(sV[fi + 4 * SKS]);
                    mma8(o[2 * g + sn], af, b0, b1);
                }
            }
        }
    }

    // normalize + write [b,n,c]
    int gi0 = i0 + rloc0, gi1 = i0 + rloc1;
    float inv0 = 1.f / lrun0, inv1 = 1.f / lrun1;
    int cb = h * HD + pc;
#pragma unroll
    for (int f = 0; f < 8; f++) {
        int col = cb + f * 8;
        if (gi0 < Nn) {
            g_AO[((size_t)b * Nn + gi0) * Cc + col]     = o[f][0] * inv0;
            g_AO[((size_t)b * Nn + gi0) * Cc + col + 1] = o[f][1] * inv0;
        }
        if (gi1 < Nn) {
            g_AO[((size_t)b * Nn + gi1) * Cc + col]     = o[f][2] * inv1;
            g_AO[((size_t)b * Nn + gi1) * Cc + col + 1] = o[f][3] * inv1;
        }
    }
}

extern "C" void kernel_launch(void* const* d_in, const int* in_sizes, int n_in,
                              void* d_out, int out_size) {
    (void)in_sizes; (void)n_in; (void)out_size;
    const float* x      = (const float*)d_in[0];
    const float* qkv_w  = (const float*)d_in[1];
    const float* qkv_b  = (const float*)d_in[2];
    const float* proj_w = (const float*)d_in[3];
    const float* proj_b = (const float*)d_in[4];
    float* out = (float*)d_out;

    static bool attr_done = false;
    if (!attr_done) {
        cudaFuncSetAttribute(attn_tf32,
                             cudaFuncAttributeMaxDynamicSharedMemorySize, ATTN_SMEM);
        attr_done = true;
    }

    init_lut_kernel<<<1, 64>>>();

    // KV GEMM (Q slab of qkv_w is dead code in the reference)
    gemm_tf32<1><<<dim3((2 * Cc) / 128, (Bsz * Nn + 127) / 128), 256>>>(
        x, qkv_w + (size_t)Cc * Cc, qkv_b + Cc, nullptr,
        Bsz * Nn, 2 * Cc, Cc);

    attn_tf32<<<dim3(17, Hh, Bsz), 128, ATTN_SMEM>>>();

    // Projection GEMM
    gemm_tf32<2><<<dim3(Cc / 128, (Bsz * Nn + 127) / 128), 256>>>(
        nullptr, proj_w, proj_b, out,
        Bsz * Nn, Cc, Cc);
}